// round 10
// baseline (speedup 1.0000x reference)
#include <cuda_runtime.h>
#include <cuda_fp16.h>
#include <cuda.h>
#include <stdint.h>

#define Cc   256
#define Hh   56
#define Ww   56
#define Oo   256
#define NIMG 32
#define MIMG 3136          // 56*56
#define KT   2304          // 256*9
#define HP   58            // 1 + 56 + 1
#define WP   64            // 1 + 56 + 7
#define NCH  36            // K chunks of 64: (kh,kw,cblk)

#define STAGE    40960     // A 32KB + B 8KB
#define OFF_A    0
#define OFF_B    32768
#define NSTG     5
#define SMEM_TOTAL (1024 + 1024 + NSTG*STAGE)

// ---------------- device globals (no runtime alloc allowed) ----------------
__device__ __align__(1024) __half g_xh[(size_t)NIMG*HP*WP*Cc]; // ~61MB fp16 plane
__device__ __align__(1024) __half g_bsign[Oo*KT];  // +-1, k=(kh*3+kw)*256+c
__device__ float g_alpha[Oo];

// ---------------- PTX helpers (all plain-sm_103-legal) ----------------
__device__ __forceinline__ uint32_t smem_u32(const void* p){
    uint32_t a;
    asm("{ .reg .u64 t; cvta.to.shared.u64 t, %1; cvt.u32.u64 %0, t; }" : "=r"(a) : "l"(p));
    return a;
}
#define MBAR_INIT(a,c)  asm volatile("mbarrier.init.shared.b64 [%0], %1;" :: "r"(a), "r"(c) : "memory")
#define MBAR_EXPECT(a,tx) asm volatile("mbarrier.arrive.expect_tx.shared.b64 _, [%0], %1;" :: "r"(a), "r"(tx) : "memory")
#define MBAR_ARRIVE(a)  asm volatile("mbarrier.arrive.shared.b64 _, [%0];" :: "r"(a) : "memory")

#define MBAR_WAIT(mbar, parity) do {                                              \
    uint32_t _m=(mbar), _p=(parity), _d;                                          \
    asm volatile("{\n\t.reg .pred p;\n\t"                                         \
        "mbarrier.try_wait.parity.acquire.cta.shared::cta.b64 p, [%1], %2;\n\t"   \
        "selp.b32 %0, 1, 0, p;\n\t}"                                              \
        : "=r"(_d) : "r"(_m), "r"(_p) : "memory");                                \
    if (!_d) {                                                                    \
        asm volatile("{\n\t.reg .pred P1;\n\t"                                    \
        "WL%=:\n\t"                                                               \
        "mbarrier.try_wait.parity.acquire.cta.shared::cta.b64 P1, [%0], %1, 0x989680;\n\t" \
        "@P1 bra.uni WD%=;\n\t"                                                   \
        "bra.uni WL%=;\n\t"                                                       \
        "WD%=:\n\t}" :: "r"(_m), "r"(_p) : "memory");                             \
    } } while(0)

#define TMA2D(dst, map, c0, c1, mbar) \
    asm volatile("cp.async.bulk.tensor.2d.shared::cta.global.tile.mbarrier::complete_tx::bytes " \
        "[%0], [%1, {%2, %3}], [%4];" \
        :: "r"(dst), "l"(map), "r"(c0), "r"(c1), "r"(mbar) : "memory")
#define TMA3D(dst, map, c0, c1, c2, mbar) \
    asm volatile("cp.async.bulk.tensor.3d.shared::cta.global.tile.mbarrier::complete_tx::bytes " \
        "[%0], [%1, {%2, %3, %4}], [%5];" \
        :: "r"(dst), "l"(map), "r"(c0), "r"(c1), "r"(c2), "r"(mbar) : "memory")

#define LDSM4(r, addr) \
    asm volatile("ldmatrix.sync.aligned.m8n8.x4.shared.b16 {%0,%1,%2,%3}, [%4];" \
        : "=r"((r)[0]), "=r"((r)[1]), "=r"((r)[2]), "=r"((r)[3]) : "r"(addr))

#define MMA(acc, a, b0, b1) \
    asm volatile("mma.sync.aligned.m16n8k16.row.col.f32.f16.f16.f32 " \
        "{%0,%1,%2,%3},{%4,%5,%6,%7},{%8,%9},{%0,%1,%2,%3};" \
        : "+f"((acc)[0]), "+f"((acc)[1]), "+f"((acc)[2]), "+f"((acc)[3]) \
        : "r"((a)[0]), "r"((a)[1]), "r"((a)[2]), "r"((a)[3]), "r"(b0), "r"(b1))

// ---------------------------------------------------------------------------
// Fused prologue. z < NIMG : padconvert blocks (x 98 spatial/32, y 4 cblk/64).
//                 z == NIMG: binarize, o = bx*4 + by (first 256 of 392).
// ---------------------------------------------------------------------------
__global__ void prologue_kernel(const float* __restrict__ x, const float* __restrict__ w){
    if (blockIdx.z == NIMG){
        const int o = blockIdx.x * 4 + blockIdx.y;
        if (o >= Oo) return;
        const float* wr = w + (size_t)o * KT;
        __shared__ float red[256];
        float s = 0.f;
        for (int i = threadIdx.x; i < KT; i += 256) s += fabsf(wr[i]);
        red[threadIdx.x] = s;
        __syncthreads();
        #pragma unroll
        for (int off = 128; off > 0; off >>= 1){
            if (threadIdx.x < off) red[threadIdx.x] += red[threadIdx.x + off];
            __syncthreads();
        }
        if (threadIdx.x == 0) g_alpha[o] = red[0] * (1.0f / (float)KT);
        const __half P1 = __float2half(1.0f);
        const __half M1 = __float2half(-1.0f);
        for (int i = threadIdx.x; i < KT; i += 256){
            int c = i / 9, r = i - c * 9;                 // w layout [O][C][3][3]
            g_bsign[(size_t)o * KT + r * Cc + c] = (wr[i] > 0.f) ? P1 : M1;
        }
        return;
    }
    // ---- NCHW f32 -> padded NHWC fp16, half2 stores; pads stay .bss-zero ----
    __shared__ float tile[64][33];
    const int s0 = blockIdx.x * 32, c0 = blockIdx.y * 64, img = blockIdx.z;
    const int t = threadIdx.x;
    #pragma unroll
    for (int j = 0; j < 8; j++){
        int ci = j * 8 + (t >> 5), si = t & 31;
        tile[ci][si] = x[((size_t)(img * Cc + c0 + ci)) * MIMG + s0 + si];
    }
    __syncthreads();
    const int cp = t & 31;                 // channel pair -> 2 contiguous halves
    #pragma unroll
    for (int j = 0; j < 4; j++){
        int si = j * 8 + (t >> 5);
        int s = s0 + si, h = s / Ww, wq = s - h * Ww;
        __half2 v = __halves2half2(__float2half(tile[2*cp][si]),
                                   __float2half(tile[2*cp + 1][si]));
        size_t dst = ((size_t)(img * HP + h + 1) * WP + (wq + 1)) * Cc + c0 + 2*cp;
        *reinterpret_cast<__half2*>(g_xh + dst) = v;
    }
}

// ---------------------------------------------------------------------------
// Producer: one chunk = (kh, kw, cblk). A: signs [256oc][64k] (32KB).
// B: x fp16 [64 w'][64c] via 3D box (c=64, w=64, h=1), OOB-zero for w>=WP.
// ---------------------------------------------------------------------------
__device__ __forceinline__ void issue_chunk(int n, int s, uint32_t data, uint32_t sb,
        int img, int t, const CUtensorMap* mW, const CUtensorMap* mX)
{
    const uint32_t st = data + (uint32_t)s * STAGE;
    const uint32_t fb = sb + s * 8;
    const int r = n >> 2, cb = n & 3;
    const int kh = r / 3, kw = r - kh * 3;
    MBAR_EXPECT(fb, STAGE);
    TMA2D(st + OFF_A, mW, n * 64, 0, fb);
    const int hc = img * HP + t + kh;      // input padded row for output row t
    TMA3D(st + OFF_B, mX, cb * 64, kw, hc, fb);
}

// ---------------------------------------------------------------------------
// Conv GEMM via mma.sync fp16. CTA tile: M=256 (oc) x N=56 (one output row),
// K=64 chunks. 8 warps: warp wo owns 32oc x 56p. TMA 5-stage pipeline.
// Smem B has 64 rows (w' 0..63); valid outputs w' 0..55 -> 7 n-frags, zero
// junk MMAs, unconditional stores. Output m = t*56 + w'.
// ---------------------------------------------------------------------------
__global__ __launch_bounds__(256, 1)
void conv_mma(const __grid_constant__ CUtensorMap mW,
              const __grid_constant__ CUtensorMap mX,
              float* __restrict__ out)
{
    extern __shared__ char smem[];
    const uint32_t sb   = (smem_u32(smem) + 1023u) & ~1023u;
    const uint32_t data = sb + 1024;
    const int tid = threadIdx.x, wid = tid >> 5, l = tid & 31;
    const int t = blockIdx.x, img = blockIdx.y;

    // full[s] = sb + s*8 ; empty[s] = sb + 64 + s*8
    if (tid == 0){
        #pragma unroll
        for (int s = 0; s < NSTG; s++){ MBAR_INIT(sb + s*8, 1); MBAR_INIT(sb + 64 + s*8, 256); }
    }
    __syncthreads();

    // ---- ldmatrix offsets: UNSWIZZLED base + XOR mask (add ks*32 pre-XOR) ----
    const int mat = l >> 3, lr = l & 7;
    uint32_t abase[2], amask[2], bbase[4], bmask[4];
    #pragma unroll
    for (int mf = 0; mf < 2; mf++){
        uint32_t row = wid * 32 + mf * 16 + (mat & 1) * 8 + lr;   // oc row
        abase[mf] = row * 128 + (mat >> 1) * 16;
        amask[mf] = (row & 7) * 16;
    }
    #pragma unroll
    for (int q = 0; q < 4; q++){
        uint32_t row = (2 * q + (mat >> 1)) * 8 + lr;             // p row (w')
        bbase[q] = row * 128 + (mat & 1) * 16;
        bmask[q] = (row & 7) * 16;
    }

    float acc[2][7][4];
    #pragma unroll
    for (int i = 0; i < 2; i++)
        #pragma unroll
        for (int j = 0; j < 7; j++)
            #pragma unroll
            for (int k = 0; k < 4; k++) acc[i][j][k] = 0.f;

    // ---- prologue: fill all stages ----
    if (tid == 0){
        #pragma unroll
        for (int n = 0; n < NSTG; n++) issue_chunk(n, n, data, sb, img, t, &mW, &mX);
    }

    int cs = 0, cph = 0;             // consumer stage/phase
    int pn = NSTG, ps = 0, pph = 0;  // producer next-chunk/stage/phase

    for (int c = 0; c < NCH; c++){
        MBAR_WAIT(sb + cs * 8, cph);
        const uint32_t stA = data + (uint32_t)cs * STAGE;
        const uint32_t stB = stA + OFF_B;

        #pragma unroll
        for (int ks = 0; ks < 4; ks++){
            uint32_t ra[2][4], rb[4][4];
            #pragma unroll
            for (int mf = 0; mf < 2; mf++)
                LDSM4(ra[mf], stA + ((abase[mf] + ks * 32) ^ amask[mf]));
            #pragma unroll
            for (int q = 0; q < 4; q++)
                LDSM4(rb[q], stB + ((bbase[q] + ks * 32) ^ bmask[q]));
            #pragma unroll
            for (int mf = 0; mf < 2; mf++)
                #pragma unroll
                for (int nf = 0; nf < 7; nf++)
                    MMA(acc[mf][nf], ra[mf], rb[nf >> 1][(nf & 1) * 2], rb[nf >> 1][(nf & 1) * 2 + 1]);
        }

        MBAR_ARRIVE(sb + 64 + cs * 8);
        cs++; if (cs == NSTG){ cs = 0; cph ^= 1; }

        if (tid == 0 && pn < NCH){
            MBAR_WAIT(sb + 64 + ps * 8, pph);      // stage drained by all consumers
            issue_chunk(pn, ps, data, sb, img, t, &mW, &mX);
            pn++; ps++; if (ps == NSTG){ ps = 0; pph ^= 1; }
        }
    }

    // ---- epilogue: fp32 alpha scale; all outputs valid, unconditional ----
    float* outp = out + (size_t)img * Oo * MIMG;
    const int mrow = t * Ww;
    #pragma unroll
    for (int mf = 0; mf < 2; mf++){
        const int oc0 = wid * 32 + mf * 16 + (l >> 2);
        const float a0 = __ldg(&g_alpha[oc0]);
        const float a1 = __ldg(&g_alpha[oc0 + 8]);
        #pragma unroll
        for (int nf = 0; nf < 7; nf++){
            const int m = mrow + nf * 8 + 2 * (l & 3);
            float2 v0 = make_float2(acc[mf][nf][0] * a0, acc[mf][nf][1] * a0);
            float2 v1 = make_float2(acc[mf][nf][2] * a1, acc[mf][nf][3] * a1);
            *reinterpret_cast<float2*>(outp + (size_t)oc0 * MIMG + m)       = v0;
            *reinterpret_cast<float2*>(outp + (size_t)(oc0 + 8) * MIMG + m) = v1;
        }
    }
}

// ---------------------------------------------------------------------------
typedef CUresult (*PFN_tmEnc)(CUtensorMap*, CUtensorMapDataType, cuuint32_t, void*,
                              const cuuint64_t*, const cuuint64_t*, const cuuint32_t*,
                              const cuuint32_t*, CUtensorMapInterleave, CUtensorMapSwizzle,
                              CUtensorMapL2promotion, CUtensorMapFloatOOBfill);

extern "C" void kernel_launch(void* const* d_in, const int* in_sizes, int n_in,
                              void* d_out, int out_size){
    const float* x = (const float*)d_in[0];
    const float* w = (const float*)d_in[1];
    if (n_in >= 2 && in_sizes[0] == Oo * KT && in_sizes[1] != Oo * KT){
        x = (const float*)d_in[1];
        w = (const float*)d_in[0];
    }

    void *pxh = nullptr, *pw = nullptr;
    cudaGetSymbolAddress(&pxh, g_xh);
    cudaGetSymbolAddress(&pw,  g_bsign);

    PFN_tmEnc enc = nullptr;
    cudaDriverEntryPointQueryResult qr;
    cudaGetDriverEntryPointByVersion("cuTensorMapEncodeTiled", (void**)&enc, 12000,
                                     cudaEnableDefault, &qr);

    CUtensorMap mW, mX;
    {   // signs: 2D [k=2304][oc=256], box (64, 256), SW128
        cuuint64_t dim[2]   = {KT, Oo};
        cuuint64_t strd[1]  = {KT * 2};
        cuuint32_t box[2]   = {64, 256};
        cuuint32_t est[2]   = {1, 1};
        enc(&mW, CU_TENSOR_MAP_DATA_TYPE_FLOAT16, 2, pw, dim, strd, box, est,
            CU_TENSOR_MAP_INTERLEAVE_NONE, CU_TENSOR_MAP_SWIZZLE_128B,
            CU_TENSOR_MAP_L2_PROMOTION_L2_128B, CU_TENSOR_MAP_FLOAT_OOB_FILL_NONE);
    }
    {   // x plane: 3D [c=256][w=64][img*h=1856], box (64, 64, 1), SW128
        cuuint64_t dim[3]   = {Cc, WP, (cuuint64_t)NIMG * HP};
        cuuint64_t strd[2]  = {Cc * 2, (cuuint64_t)WP * Cc * 2};
        cuuint32_t box[3]   = {64, 64, 1};
        cuuint32_t est[3]   = {1, 1, 1};
        enc(&mX, CU_TENSOR_MAP_DATA_TYPE_FLOAT16, 3, pxh, dim, strd, box, est,
            CU_TENSOR_MAP_INTERLEAVE_NONE, CU_TENSOR_MAP_SWIZZLE_128B,
            CU_TENSOR_MAP_L2_PROMOTION_L2_128B, CU_TENSOR_MAP_FLOAT_OOB_FILL_NONE);
    }

    cudaFuncSetAttribute(conv_mma, cudaFuncAttributeMaxDynamicSharedMemorySize, SMEM_TOTAL);

    prologue_kernel<<<dim3(98, 4, NIMG + 1), 256>>>(x, w);
    conv_mma<<<dim3(56, NIMG), 256, SMEM_TOTAL>>>(mW, mX, (float*)d_out);
}

// round 11
// speedup vs baseline: 1.0456x; 1.0456x over previous
#include <cuda_runtime.h>
#include <cuda_fp16.h>
#include <cuda.h>
#include <stdint.h>

#define Cc   256
#define Hh   56
#define Ww   56
#define Oo   256
#define NIMG 32
#define MIMG 3136          // 56*56
#define KT   2304          // 256*9
#define HP   58            // 1 + 56 + 1
#define WP   64            // 1 + 56 + 7
#define NCH  36            // K chunks of 64: (kh,kw,cblk)

#define STAGE    40960     // A 32KB + B 8KB
#define OFF_A    0
#define OFF_B    32768
#define NSTG     2
#define SMEM_TOTAL (1024 + 1024 + NSTG*STAGE)   // ~84KB -> 2 CTAs/SM

// ---------------- device globals (no runtime alloc allowed) ----------------
__device__ __align__(1024) __half g_xh[(size_t)NIMG*HP*WP*Cc]; // ~61MB fp16 plane
__device__ __align__(1024) __half g_bsign[Oo*KT];  // +-1, k=(kh*3+kw)*256+c
__device__ float g_alpha[Oo];

// ---------------- PTX helpers (all plain-sm_103-legal) ----------------
__device__ __forceinline__ uint32_t smem_u32(const void* p){
    uint32_t a;
    asm("{ .reg .u64 t; cvta.to.shared.u64 t, %1; cvt.u32.u64 %0, t; }" : "=r"(a) : "l"(p));
    return a;
}
#define MBAR_INIT(a,c)  asm volatile("mbarrier.init.shared.b64 [%0], %1;" :: "r"(a), "r"(c) : "memory")
#define MBAR_EXPECT(a,tx) asm volatile("mbarrier.arrive.expect_tx.shared.b64 _, [%0], %1;" :: "r"(a), "r"(tx) : "memory")
#define MBAR_ARRIVE(a)  asm volatile("mbarrier.arrive.shared.b64 _, [%0];" :: "r"(a) : "memory")

#define MBAR_WAIT(mbar, parity) do {                                              \
    uint32_t _m=(mbar), _p=(parity), _d;                                          \
    asm volatile("{\n\t.reg .pred p;\n\t"                                         \
        "mbarrier.try_wait.parity.acquire.cta.shared::cta.b64 p, [%1], %2;\n\t"   \
        "selp.b32 %0, 1, 0, p;\n\t}"                                              \
        : "=r"(_d) : "r"(_m), "r"(_p) : "memory");                                \
    if (!_d) {                                                                    \
        asm volatile("{\n\t.reg .pred P1;\n\t"                                    \
        "WL%=:\n\t"                                                               \
        "mbarrier.try_wait.parity.acquire.cta.shared::cta.b64 P1, [%0], %1, 0x989680;\n\t" \
        "@P1 bra.uni WD%=;\n\t"                                                   \
        "bra.uni WL%=;\n\t"                                                       \
        "WD%=:\n\t}" :: "r"(_m), "r"(_p) : "memory");                             \
    } } while(0)

#define TMA2D(dst, map, c0, c1, mbar) \
    asm volatile("cp.async.bulk.tensor.2d.shared::cta.global.tile.mbarrier::complete_tx::bytes " \
        "[%0], [%1, {%2, %3}], [%4];" \
        :: "r"(dst), "l"(map), "r"(c0), "r"(c1), "r"(mbar) : "memory")
#define TMA3D(dst, map, c0, c1, c2, mbar) \
    asm volatile("cp.async.bulk.tensor.3d.shared::cta.global.tile.mbarrier::complete_tx::bytes " \
        "[%0], [%1, {%2, %3, %4}], [%5];" \
        :: "r"(dst), "l"(map), "r"(c0), "r"(c1), "r"(c2), "r"(mbar) : "memory")

#define LDSM4(r, addr) \
    asm volatile("ldmatrix.sync.aligned.m8n8.x4.shared.b16 {%0,%1,%2,%3}, [%4];" \
        : "=r"((r)[0]), "=r"((r)[1]), "=r"((r)[2]), "=r"((r)[3]) : "r"(addr))

#define MMA(acc, a, b0, b1) \
    asm volatile("mma.sync.aligned.m16n8k16.row.col.f32.f16.f16.f32 " \
        "{%0,%1,%2,%3},{%4,%5,%6,%7},{%8,%9},{%0,%1,%2,%3};" \
        : "+f"((acc)[0]), "+f"((acc)[1]), "+f"((acc)[2]), "+f"((acc)[3]) \
        : "r"((a)[0]), "r"((a)[1]), "r"((a)[2]), "r"((a)[3]), "r"(b0), "r"(b1))

// ---------------------------------------------------------------------------
// Fused prologue. z < NIMG : padconvert blocks (x 98 spatial/32, y 4 cblk/64).
//                 z == NIMG: binarize, o = bx*4 + by (first 256 of 392).
// ---------------------------------------------------------------------------
__global__ void prologue_kernel(const float* __restrict__ x, const float* __restrict__ w){
    if (blockIdx.z == NIMG){
        const int o = blockIdx.x * 4 + blockIdx.y;
        if (o >= Oo) return;
        const float* wr = w + (size_t)o * KT;
        __shared__ float red[256];
        float s = 0.f;
        for (int i = threadIdx.x; i < KT; i += 256) s += fabsf(wr[i]);
        red[threadIdx.x] = s;
        __syncthreads();
        #pragma unroll
        for (int off = 128; off > 0; off >>= 1){
            if (threadIdx.x < off) red[threadIdx.x] += red[threadIdx.x + off];
            __syncthreads();
        }
        if (threadIdx.x == 0) g_alpha[o] = red[0] * (1.0f / (float)KT);
        const __half P1 = __float2half(1.0f);
        const __half M1 = __float2half(-1.0f);
        for (int i = threadIdx.x; i < KT; i += 256){
            int c = i / 9, r = i - c * 9;                 // w layout [O][C][3][3]
            g_bsign[(size_t)o * KT + r * Cc + c] = (wr[i] > 0.f) ? P1 : M1;
        }
        return;
    }
    // ---- NCHW f32 -> padded NHWC fp16, half2 stores; pads stay .bss-zero ----
    __shared__ float tile[64][33];
    const int s0 = blockIdx.x * 32, c0 = blockIdx.y * 64, img = blockIdx.z;
    const int t = threadIdx.x;
    #pragma unroll
    for (int j = 0; j < 8; j++){
        int ci = j * 8 + (t >> 5), si = t & 31;
        tile[ci][si] = x[((size_t)(img * Cc + c0 + ci)) * MIMG + s0 + si];
    }
    __syncthreads();
    const int cp = t & 31;                 // channel pair -> 2 contiguous halves
    #pragma unroll
    for (int j = 0; j < 4; j++){
        int si = j * 8 + (t >> 5);
        int s = s0 + si, h = s / Ww, wq = s - h * Ww;
        __half2 v = __halves2half2(__float2half(tile[2*cp][si]),
                                   __float2half(tile[2*cp + 1][si]));
        size_t dst = ((size_t)(img * HP + h + 1) * WP + (wq + 1)) * Cc + c0 + 2*cp;
        *reinterpret_cast<__half2*>(g_xh + dst) = v;
    }
}

// ---------------------------------------------------------------------------
// Producer: one chunk = (kh, kw, cblk). A: signs [256oc][64k] (32KB).
// B: x fp16 [64 w'][64c] via 3D box (c=64, w=64, h=1), OOB-zero for w>=WP.
// ---------------------------------------------------------------------------
__device__ __forceinline__ void issue_chunk(int n, int s, uint32_t data, uint32_t sb,
        int img, int t, const CUtensorMap* mW, const CUtensorMap* mX)
{
    const uint32_t st = data + (uint32_t)s * STAGE;
    const uint32_t fb = sb + s * 8;
    const int r = n >> 2, cb = n & 3;
    const int kh = r / 3, kw = r - kh * 3;
    MBAR_EXPECT(fb, STAGE);
    TMA2D(st + OFF_A, mW, n * 64, 0, fb);
    const int hc = img * HP + t + kh;      // input padded row for output row t
    TMA3D(st + OFF_B, mX, cb * 64, kw, hc, fb);
}

// ---------------------------------------------------------------------------
// Conv GEMM via mma.sync fp16. CTA tile: M=256 (oc) x N=56 (one output row),
// K=64 chunks. 8 warps: warp wo owns 32oc x 56p. 2-stage TMA pipeline,
// 2 CTAs/SM so sibling CTA hides barrier/TMA bubbles in the tensor pipe.
// Output m = t*56 + w'.
// ---------------------------------------------------------------------------
__global__ __launch_bounds__(256, 2)
void conv_mma(const __grid_constant__ CUtensorMap mW,
              const __grid_constant__ CUtensorMap mX,
              float* __restrict__ out)
{
    extern __shared__ char smem[];
    const uint32_t sb   = (smem_u32(smem) + 1023u) & ~1023u;
    const uint32_t data = sb + 1024;
    const int tid = threadIdx.x, wid = tid >> 5, l = tid & 31;
    const int t = blockIdx.x, img = blockIdx.y;

    // full[s] = sb + s*8 ; empty[s] = sb + 64 + s*8
    if (tid == 0){
        #pragma unroll
        for (int s = 0; s < NSTG; s++){ MBAR_INIT(sb + s*8, 1); MBAR_INIT(sb + 64 + s*8, 256); }
    }
    __syncthreads();

    // ---- ldmatrix offsets: UNSWIZZLED base + XOR mask (add ks*32 pre-XOR) ----
    const int mat = l >> 3, lr = l & 7;
    uint32_t abase[2], amask[2], bbase[4], bmask[4];
    #pragma unroll
    for (int mf = 0; mf < 2; mf++){
        uint32_t row = wid * 32 + mf * 16 + (mat & 1) * 8 + lr;   // oc row
        abase[mf] = row * 128 + (mat >> 1) * 16;
        amask[mf] = (row & 7) * 16;
    }
    #pragma unroll
    for (int q = 0; q < 4; q++){
        uint32_t row = (2 * q + (mat >> 1)) * 8 + lr;             // p row (w')
        bbase[q] = row * 128 + (mat & 1) * 16;
        bmask[q] = (row & 7) * 16;
    }

    float acc[2][7][4];
    #pragma unroll
    for (int i = 0; i < 2; i++)
        #pragma unroll
        for (int j = 0; j < 7; j++)
            #pragma unroll
            for (int k = 0; k < 4; k++) acc[i][j][k] = 0.f;

    // ---- prologue: fill both stages ----
    if (tid == 0){
        #pragma unroll
        for (int n = 0; n < NSTG; n++) issue_chunk(n, n, data, sb, img, t, &mW, &mX);
    }

    int cs = 0, cph = 0;             // consumer stage/phase
    int pn = NSTG, ps = 0, pph = 0;  // producer next-chunk/stage/phase

    for (int c = 0; c < NCH; c++){
        MBAR_WAIT(sb + cs * 8, cph);
        const uint32_t stA = data + (uint32_t)cs * STAGE;
        const uint32_t stB = stA + OFF_B;

        #pragma unroll
        for (int ks = 0; ks < 4; ks++){
            uint32_t ra[2][4], rb[4][4];
            #pragma unroll
            for (int mf = 0; mf < 2; mf++)
                LDSM4(ra[mf], stA + ((abase[mf] + ks * 32) ^ amask[mf]));
            #pragma unroll
            for (int q = 0; q < 4; q++)
                LDSM4(rb[q], stB + ((bbase[q] + ks * 32) ^ bmask[q]));
            #pragma unroll
            for (int mf = 0; mf < 2; mf++)
                #pragma unroll
                for (int nf = 0; nf < 7; nf++)
                    MMA(acc[mf][nf], ra[mf], rb[nf >> 1][(nf & 1) * 2], rb[nf >> 1][(nf & 1) * 2 + 1]);
        }

        MBAR_ARRIVE(sb + 64 + cs * 8);
        cs++; if (cs == NSTG){ cs = 0; cph ^= 1; }

        if (tid == 0 && pn < NCH){
            MBAR_WAIT(sb + 64 + ps * 8, pph);      // stage drained by all consumers
            issue_chunk(pn, ps, data, sb, img, t, &mW, &mX);
            pn++; ps++; if (ps == NSTG){ ps = 0; pph ^= 1; }
        }
    }

    // ---- epilogue: fp32 alpha scale; all outputs valid, unconditional ----
    float* outp = out + (size_t)img * Oo * MIMG;
    const int mrow = t * Ww;
    #pragma unroll
    for (int mf = 0; mf < 2; mf++){
        const int oc0 = wid * 32 + mf * 16 + (l >> 2);
        const float a0 = __ldg(&g_alpha[oc0]);
        const float a1 = __ldg(&g_alpha[oc0 + 8]);
        #pragma unroll
        for (int nf = 0; nf < 7; nf++){
            const int m = mrow + nf * 8 + 2 * (l & 3);
            float2 v0 = make_float2(acc[mf][nf][0] * a0, acc[mf][nf][1] * a0);
            float2 v1 = make_float2(acc[mf][nf][2] * a1, acc[mf][nf][3] * a1);
            *reinterpret_cast<float2*>(outp + (size_t)oc0 * MIMG + m)       = v0;
            *reinterpret_cast<float2*>(outp + (size_t)(oc0 + 8) * MIMG + m) = v1;
        }
    }
}

// ---------------------------------------------------------------------------
typedef CUresult (*PFN_tmEnc)(CUtensorMap*, CUtensorMapDataType, cuuint32_t, void*,
                              const cuuint64_t*, const cuuint64_t*, const cuuint32_t*,
                              const cuuint32_t*, CUtensorMapInterleave, CUtensorMapSwizzle,
                              CUtensorMapL2promotion, CUtensorMapFloatOOBfill);

extern "C" void kernel_launch(void* const* d_in, const int* in_sizes, int n_in,
                              void* d_out, int out_size){
    const float* x = (const float*)d_in[0];
    const float* w = (const float*)d_in[1];
    if (n_in >= 2 && in_sizes[0] == Oo * KT && in_sizes[1] != Oo * KT){
        x = (const float*)d_in[1];
        w = (const float*)d_in[0];
    }

    void *pxh = nullptr, *pw = nullptr;
    cudaGetSymbolAddress(&pxh, g_xh);
    cudaGetSymbolAddress(&pw,  g_bsign);

    PFN_tmEnc enc = nullptr;
    cudaDriverEntryPointQueryResult qr;
    cudaGetDriverEntryPointByVersion("cuTensorMapEncodeTiled", (void**)&enc, 12000,
                                     cudaEnableDefault, &qr);

    CUtensorMap mW, mX;
    {   // signs: 2D [k=2304][oc=256], box (64, 256), SW128
        cuuint64_t dim[2]   = {KT, Oo};
        cuuint64_t strd[1]  = {KT * 2};
        cuuint32_t box[2]   = {64, 256};
        cuuint32_t est[2]   = {1, 1};
        enc(&mW, CU_TENSOR_MAP_DATA_TYPE_FLOAT16, 2, pw, dim, strd, box, est,
            CU_TENSOR_MAP_INTERLEAVE_NONE, CU_TENSOR_MAP_SWIZZLE_128B,
            CU_TENSOR_MAP_L2_PROMOTION_L2_128B, CU_TENSOR_MAP_FLOAT_OOB_FILL_NONE);
    }
    {   // x plane: 3D [c=256][w=64][img*h=1856], box (64, 64, 1), SW128
        cuuint64_t dim[3]   = {Cc, WP, (cuuint64_t)NIMG * HP};
        cuuint64_t strd[2]  = {Cc * 2, (cuuint64_t)WP * Cc * 2};
        cuuint32_t box[3]   = {64, 64, 1};
        cuuint32_t est[3]   = {1, 1, 1};
        enc(&mX, CU_TENSOR_MAP_DATA_TYPE_FLOAT16, 3, pxh, dim, strd, box, est,
            CU_TENSOR_MAP_INTERLEAVE_NONE, CU_TENSOR_MAP_SWIZZLE_128B,
            CU_TENSOR_MAP_L2_PROMOTION_L2_128B, CU_TENSOR_MAP_FLOAT_OOB_FILL_NONE);
    }

    cudaFuncSetAttribute(conv_mma, cudaFuncAttributeMaxDynamicSharedMemorySize, SMEM_TOTAL);

    prologue_kernel<<<dim3(98, 4, NIMG + 1), 256>>>(x, w);
    conv_mma<<<dim3(56, NIMG), 256, SMEM_TOTAL>>>(mW, mX, (float*)d_out);
}

// round 12
// speedup vs baseline: 1.0750x; 1.0281x over previous
#include <cuda_runtime.h>
#include <cuda_fp16.h>
#include <cuda.h>
#include <stdint.h>

#define Cc   256
#define Hh   56
#define Ww   56
#define Oo   256
#define NIMG 32
#define MIMG 3136          // 56*56
#define KT   2304          // 256*9
#define HP   58            // 1 + 56 + 1
#define WP   64            // 1 + 56 + 7
#define NCH  36            // K chunks of 64: (kh,kw,cblk)

#define STAGE    40960     // A 32KB + B 8KB
#define OFF_A    0
#define OFF_B    32768
#define NSTG     2
#define SMEM_TOTAL (1024 + 1024 + NSTG*STAGE)   // ~82KB -> 2 CTAs/SM

#define NTHR 128           // 4 warps; 1 warp per SMSP per CTA

// ---------------- device globals (no runtime alloc allowed) ----------------
__device__ __align__(1024) __half g_xh[(size_t)NIMG*HP*WP*Cc]; // ~61MB fp16 plane
__device__ __align__(1024) __half g_bsign[Oo*KT];  // +-1, k=(kh*3+kw)*256+c
__device__ float g_alpha[Oo];

// ---------------- PTX helpers (all plain-sm_103-legal) ----------------
__device__ __forceinline__ uint32_t smem_u32(const void* p){
    uint32_t a;
    asm("{ .reg .u64 t; cvta.to.shared.u64 t, %1; cvt.u32.u64 %0, t; }" : "=r"(a) : "l"(p));
    return a;
}
#define MBAR_INIT(a,c)  asm volatile("mbarrier.init.shared.b64 [%0], %1;" :: "r"(a), "r"(c) : "memory")
#define MBAR_EXPECT(a,tx) asm volatile("mbarrier.arrive.expect_tx.shared.b64 _, [%0], %1;" :: "r"(a), "r"(tx) : "memory")
#define MBAR_ARRIVE(a)  asm volatile("mbarrier.arrive.shared.b64 _, [%0];" :: "r"(a) : "memory")

#define MBAR_WAIT(mbar, parity) do {                                              \
    uint32_t _m=(mbar), _p=(parity), _d;                                          \
    asm volatile("{\n\t.reg .pred p;\n\t"                                         \
        "mbarrier.try_wait.parity.acquire.cta.shared::cta.b64 p, [%1], %2;\n\t"   \
        "selp.b32 %0, 1, 0, p;\n\t}"                                              \
        : "=r"(_d) : "r"(_m), "r"(_p) : "memory");                                \
    if (!_d) {                                                                    \
        asm volatile("{\n\t.reg .pred P1;\n\t"                                    \
        "WL%=:\n\t"                                                               \
        "mbarrier.try_wait.parity.acquire.cta.shared::cta.b64 P1, [%0], %1, 0x989680;\n\t" \
        "@P1 bra.uni WD%=;\n\t"                                                   \
        "bra.uni WL%=;\n\t"                                                       \
        "WD%=:\n\t}" :: "r"(_m), "r"(_p) : "memory");                             \
    } } while(0)

#define TMA2D(dst, map, c0, c1, mbar) \
    asm volatile("cp.async.bulk.tensor.2d.shared::cta.global.tile.mbarrier::complete_tx::bytes " \
        "[%0], [%1, {%2, %3}], [%4];" \
        :: "r"(dst), "l"(map), "r"(c0), "r"(c1), "r"(mbar) : "memory")
#define TMA3D(dst, map, c0, c1, c2, mbar) \
    asm volatile("cp.async.bulk.tensor.3d.shared::cta.global.tile.mbarrier::complete_tx::bytes " \
        "[%0], [%1, {%2, %3, %4}], [%5];" \
        :: "r"(dst), "l"(map), "r"(c0), "r"(c1), "r"(c2), "r"(mbar) : "memory")

#define LDSM4(r, addr) \
    asm volatile("ldmatrix.sync.aligned.m8n8.x4.shared.b16 {%0,%1,%2,%3}, [%4];" \
        : "=r"((r)[0]), "=r"((r)[1]), "=r"((r)[2]), "=r"((r)[3]) : "r"(addr))

#define MMA(acc, a, b0, b1) \
    asm volatile("mma.sync.aligned.m16n8k16.row.col.f32.f16.f16.f32 " \
        "{%0,%1,%2,%3},{%4,%5,%6,%7},{%8,%9},{%0,%1,%2,%3};" \
        : "+f"((acc)[0]), "+f"((acc)[1]), "+f"((acc)[2]), "+f"((acc)[3]) \
        : "r"((a)[0]), "r"((a)[1]), "r"((a)[2]), "r"((a)[3]), "r"(b0), "r"(b1))

// ---------------------------------------------------------------------------
// Fused prologue. z < NIMG : padconvert blocks (x 98 spatial/32, y 4 cblk/64).
//                 z == NIMG: binarize, o = bx*4 + by (first 256 of 392).
// ---------------------------------------------------------------------------
__global__ void prologue_kernel(const float* __restrict__ x, const float* __restrict__ w){
    if (blockIdx.z == NIMG){
        const int o = blockIdx.x * 4 + blockIdx.y;
        if (o >= Oo) return;
        const float* wr = w + (size_t)o * KT;
        __shared__ float red[256];
        float s = 0.f;
        for (int i = threadIdx.x; i < KT; i += 256) s += fabsf(wr[i]);
        red[threadIdx.x] = s;
        __syncthreads();
        #pragma unroll
        for (int off = 128; off > 0; off >>= 1){
            if (threadIdx.x < off) red[threadIdx.x] += red[threadIdx.x + off];
            __syncthreads();
        }
        if (threadIdx.x == 0) g_alpha[o] = red[0] * (1.0f / (float)KT);
        const __half P1 = __float2half(1.0f);
        const __half M1 = __float2half(-1.0f);
        for (int i = threadIdx.x; i < KT; i += 256){
            int c = i / 9, r = i - c * 9;                 // w layout [O][C][3][3]
            g_bsign[(size_t)o * KT + r * Cc + c] = (wr[i] > 0.f) ? P1 : M1;
        }
        return;
    }
    // ---- NCHW f32 -> padded NHWC fp16, half2 stores; pads stay .bss-zero ----
    __shared__ float tile[64][33];
    const int s0 = blockIdx.x * 32, c0 = blockIdx.y * 64, img = blockIdx.z;
    const int t = threadIdx.x;
    #pragma unroll
    for (int j = 0; j < 8; j++){
        int ci = j * 8 + (t >> 5), si = t & 31;
        tile[ci][si] = x[((size_t)(img * Cc + c0 + ci)) * MIMG + s0 + si];
    }
    __syncthreads();
    const int cp = t & 31;                 // channel pair -> 2 contiguous halves
    #pragma unroll
    for (int j = 0; j < 4; j++){
        int si = j * 8 + (t >> 5);
        int s = s0 + si, h = s / Ww, wq = s - h * Ww;
        __half2 v = __halves2half2(__float2half(tile[2*cp][si]),
                                   __float2half(tile[2*cp + 1][si]));
        size_t dst = ((size_t)(img * HP + h + 1) * WP + (wq + 1)) * Cc + c0 + 2*cp;
        *reinterpret_cast<__half2*>(g_xh + dst) = v;
    }
}

// ---------------------------------------------------------------------------
// Producer: one chunk = (kh, kw, cblk). A: signs [256oc][64k] (32KB).
// B: x fp16 [64 w'][64c] via 3D box (c=64, w=64, h=1), OOB-zero for w>=WP.
// ---------------------------------------------------------------------------
__device__ __forceinline__ void issue_chunk(int n, int s, uint32_t data, uint32_t sb,
        int img, int t, const CUtensorMap* mW, const CUtensorMap* mX)
{
    const uint32_t st = data + (uint32_t)s * STAGE;
    const uint32_t fb = sb + s * 8;
    const int r = n >> 2, cb = n & 3;
    const int kh = r / 3, kw = r - kh * 3;
    MBAR_EXPECT(fb, STAGE);
    TMA2D(st + OFF_A, mW, n * 64, 0, fb);
    const int hc = img * HP + t + kh;      // input padded row for output row t
    TMA3D(st + OFF_B, mX, cb * 64, kw, hc, fb);
}

// ---------------------------------------------------------------------------
// Conv GEMM via mma.sync fp16. CTA tile: M=256 (oc) x N=56 (one output row),
// K=64 chunks. 4 warps; warp w owns 64oc x 56p -> A read once, B dup 4x:
// smem reads 64KB/chunk/CTA, under the 128 B/cyc crossbar with 2 CTAs/SM.
// 2-stage TMA pipeline; sibling CTA (1 warp/SMSP each) hides bubbles.
// Output m = t*56 + w'.
// ---------------------------------------------------------------------------
__global__ __launch_bounds__(NTHR, 2)
void conv_mma(const __grid_constant__ CUtensorMap mW,
              const __grid_constant__ CUtensorMap mX,
              float* __restrict__ out)
{
    extern __shared__ char smem[];
    const uint32_t sb   = (smem_u32(smem) + 1023u) & ~1023u;
    const uint32_t data = sb + 1024;
    const int tid = threadIdx.x, wid = tid >> 5, l = tid & 31;
    const int t = blockIdx.x, img = blockIdx.y;

    // full[s] = sb + s*8 ; empty[s] = sb + 64 + s*8
    if (tid == 0){
        #pragma unroll
        for (int s = 0; s < NSTG; s++){ MBAR_INIT(sb + s*8, 1); MBAR_INIT(sb + 64 + s*8, NTHR); }
    }
    __syncthreads();

    // ---- ldmatrix offsets: UNSWIZZLED base + XOR mask (add ks*32 pre-XOR) ----
    const int mat = l >> 3, lr = l & 7;
    uint32_t abase[4], amask[4], bbase[4], bmask[4];
    #pragma unroll
    for (int mf = 0; mf < 4; mf++){
        uint32_t row = wid * 64 + mf * 16 + (mat & 1) * 8 + lr;   // oc row
        abase[mf] = row * 128 + (mat >> 1) * 16;
        amask[mf] = (row & 7) * 16;
    }
    #pragma unroll
    for (int q = 0; q < 4; q++){
        uint32_t row = (2 * q + (mat >> 1)) * 8 + lr;             // p row (w')
        bbase[q] = row * 128 + (mat & 1) * 16;
        bmask[q] = (row & 7) * 16;
    }

    float acc[4][7][4];
    #pragma unroll
    for (int i = 0; i < 4; i++)
        #pragma unroll
        for (int j = 0; j < 7; j++)
            #pragma unroll
            for (int k = 0; k < 4; k++) acc[i][j][k] = 0.f;

    // ---- prologue: fill both stages ----
    if (tid == 0){
        #pragma unroll
        for (int n = 0; n < NSTG; n++) issue_chunk(n, n, data, sb, img, t, &mW, &mX);
    }

    int cs = 0, cph = 0;             // consumer stage/phase
    int pn = NSTG, ps = 0, pph = 0;  // producer next-chunk/stage/phase

    for (int c = 0; c < NCH; c++){
        MBAR_WAIT(sb + cs * 8, cph);
        const uint32_t stA = data + (uint32_t)cs * STAGE;
        const uint32_t stB = stA + OFF_B;

        #pragma unroll
        for (int ks = 0; ks < 4; ks++){
            uint32_t ra[4][4], rb[4][4];
            #pragma unroll
            for (int mf = 0; mf < 4; mf++)
                LDSM4(ra[mf], stA + ((abase[mf] + ks * 32) ^ amask[mf]));
            #pragma unroll
            for (int q = 0; q < 4; q++)
                LDSM4(rb[q], stB + ((bbase[q] + ks * 32) ^ bmask[q]));
            #pragma unroll
            for (int mf = 0; mf < 4; mf++)
                #pragma unroll
                for (int nf = 0; nf < 7; nf++)
                    MMA(acc[mf][nf], ra[mf], rb[nf >> 1][(nf & 1) * 2], rb[nf >> 1][(nf & 1) * 2 + 1]);
        }

        MBAR_ARRIVE(sb + 64 + cs * 8);
        cs++; if (cs == NSTG){ cs = 0; cph ^= 1; }

        if (tid == 0 && pn < NCH){
            MBAR_WAIT(sb + 64 + ps * 8, pph);      // stage drained by all consumers
            issue_chunk(pn, ps, data, sb, img, t, &mW, &mX);
            pn++; ps++; if (ps == NSTG){ ps = 0; pph ^= 1; }
        }
    }

    // ---- epilogue: fp32 alpha scale; all outputs valid, unconditional ----
    float* outp = out + (size_t)img * Oo * MIMG;
    const int mrow = t * Ww;
    #pragma unroll
    for (int mf = 0; mf < 4; mf++){
        const int oc0 = wid * 64 + mf * 16 + (l >> 2);
        const float a0 = __ldg(&g_alpha[oc0]);
        const float a1 = __ldg(&g_alpha[oc0 + 8]);
        #pragma unroll
        for (int nf = 0; nf < 7; nf++){
            const int m = mrow + nf * 8 + 2 * (l & 3);
            float2 v0 = make_float2(acc[mf][nf][0] * a0, acc[mf][nf][1] * a0);
            float2 v1 = make_float2(acc[mf][nf][2] * a1, acc[mf][nf][3] * a1);
            *reinterpret_cast<float2*>(outp + (size_t)oc0 * MIMG + m)       = v0;
            *reinterpret_cast<float2*>(outp + (size_t)(oc0 + 8) * MIMG + m) = v1;
        }
    }
}

// ---------------------------------------------------------------------------
typedef CUresult (*PFN_tmEnc)(CUtensorMap*, CUtensorMapDataType, cuuint32_t, void*,
                              const cuuint64_t*, const cuuint64_t*, const cuuint32_t*,
                              const cuuint32_t*, CUtensorMapInterleave, CUtensorMapSwizzle,
                              CUtensorMapL2promotion, CUtensorMapFloatOOBfill);

extern "C" void kernel_launch(void* const* d_in, const int* in_sizes, int n_in,
                              void* d_out, int out_size){
    const float* x = (const float*)d_in[0];
    const float* w = (const float*)d_in[1];
    if (n_in >= 2 && in_sizes[0] == Oo * KT && in_sizes[1] != Oo * KT){
        x = (const float*)d_in[1];
        w = (const float*)d_in[0];
    }

    void *pxh = nullptr, *pw = nullptr;
    cudaGetSymbolAddress(&pxh, g_xh);
    cudaGetSymbolAddress(&pw,  g_bsign);

    PFN_tmEnc enc = nullptr;
    cudaDriverEntryPointQueryResult qr;
    cudaGetDriverEntryPointByVersion("cuTensorMapEncodeTiled", (void**)&enc, 12000,
                                     cudaEnableDefault, &qr);

    CUtensorMap mW, mX;
    {   // signs: 2D [k=2304][oc=256], box (64, 256), SW128
        cuuint64_t dim[2]   = {KT, Oo};
        cuuint64_t strd[1]  = {KT * 2};
        cuuint32_t box[2]   = {64, 256};
        cuuint32_t est[2]   = {1, 1};
        enc(&mW, CU_TENSOR_MAP_DATA_TYPE_FLOAT16, 2, pw, dim, strd, box, est,
            CU_TENSOR_MAP_INTERLEAVE_NONE, CU_TENSOR_MAP_SWIZZLE_128B,
            CU_TENSOR_MAP_L2_PROMOTION_L2_128B, CU_TENSOR_MAP_FLOAT_OOB_FILL_NONE);
    }
    {   // x plane: 3D [c=256][w=64][img*h=1856], box (64, 64, 1), SW128
        cuuint64_t dim[3]   = {Cc, WP, (cuuint64_t)NIMG * HP};
        cuuint64_t strd[2]  = {Cc * 2, (cuuint64_t)WP * Cc * 2};
        cuuint32_t box[3]   = {64, 64, 1};
        cuuint32_t est[3]   = {1, 1, 1};
        enc(&mX, CU_TENSOR_MAP_DATA_TYPE_FLOAT16, 3, pxh, dim, strd, box, est,
            CU_TENSOR_MAP_INTERLEAVE_NONE, CU_TENSOR_MAP_SWIZZLE_128B,
            CU_TENSOR_MAP_L2_PROMOTION_L2_128B, CU_TENSOR_MAP_FLOAT_OOB_FILL_NONE);
    }

    cudaFuncSetAttribute(conv_mma, cudaFuncAttributeMaxDynamicSharedMemorySize, SMEM_TOTAL);

    prologue_kernel<<<dim3(98, 4, NIMG + 1), 256>>>(x, w);
    conv_mma<<<dim3(56, NIMG), NTHR, SMEM_TOTAL>>>(mW, mX, (float*)d_out);
}

// round 13
// speedup vs baseline: 1.0936x; 1.0174x over previous
#include <cuda_runtime.h>
#include <cuda_fp16.h>
#include <cuda.h>
#include <stdint.h>

#define Cc   256
#define Hh   56
#define Ww   56
#define Oo   256
#define NIMG 32
#define MIMG 3136          // 56*56
#define KT   2304          // 256*9
#define HP   58            // 1 + 56 + 1
#define WP   64            // 1 + 56 + 7
#define NCH  36            // K chunks of 64: (kh,kw,cblk)

#define STAGE    32768     // A 16KB + B0 8KB + B1 8KB
#define OFF_A    0
#define OFF_B0   16384
#define OFF_B1   24576
#define NSTG     2
#define SMEM_TOTAL (1024 + 1024 + NSTG*STAGE)   // ~66KB -> 2 CTAs/SM

#define NTHR 128           // 4 warps; 1 warp per SMSP per CTA

// ---------------- device globals (no runtime alloc allowed) ----------------
__device__ __align__(1024) __half g_xh[(size_t)NIMG*HP*WP*Cc]; // ~61MB fp16 plane
__device__ __align__(1024) __half g_bsign[Oo*KT];  // +-1, k=(kh*3+kw)*256+c
__device__ float g_alpha[Oo];

// ---------------- PTX helpers (all plain-sm_103-legal) ----------------
__device__ __forceinline__ uint32_t smem_u32(const void* p){
    uint32_t a;
    asm("{ .reg .u64 t; cvta.to.shared.u64 t, %1; cvt.u32.u64 %0, t; }" : "=r"(a) : "l"(p));
    return a;
}
#define MBAR_INIT(a,c)  asm volatile("mbarrier.init.shared.b64 [%0], %1;" :: "r"(a), "r"(c) : "memory")
#define MBAR_EXPECT(a,tx) asm volatile("mbarrier.arrive.expect_tx.shared.b64 _, [%0], %1;" :: "r"(a), "r"(tx) : "memory")
#define MBAR_ARRIVE(a)  asm volatile("mbarrier.arrive.shared.b64 _, [%0];" :: "r"(a) : "memory")

#define MBAR_WAIT(mbar, parity) do {                                              \
    uint32_t _m=(mbar), _p=(parity), _d;                                          \
    asm volatile("{\n\t.reg .pred p;\n\t"                                         \
        "mbarrier.try_wait.parity.acquire.cta.shared::cta.b64 p, [%1], %2;\n\t"   \
        "selp.b32 %0, 1, 0, p;\n\t}"                                              \
        : "=r"(_d) : "r"(_m), "r"(_p) : "memory");                                \
    if (!_d) {                                                                    \
        asm volatile("{\n\t.reg .pred P1;\n\t"                                    \
        "WL%=:\n\t"                                                               \
        "mbarrier.try_wait.parity.acquire.cta.shared::cta.b64 P1, [%0], %1, 0x989680;\n\t" \
        "@P1 bra.uni WD%=;\n\t"                                                   \
        "bra.uni WL%=;\n\t"                                                       \
        "WD%=:\n\t}" :: "r"(_m), "r"(_p) : "memory");                             \
    } } while(0)

#define TMA2D(dst, map, c0, c1, mbar) \
    asm volatile("cp.async.bulk.tensor.2d.shared::cta.global.tile.mbarrier::complete_tx::bytes " \
        "[%0], [%1, {%2, %3}], [%4];" \
        :: "r"(dst), "l"(map), "r"(c0), "r"(c1), "r"(mbar) : "memory")
#define TMA3D(dst, map, c0, c1, c2, mbar) \
    asm volatile("cp.async.bulk.tensor.3d.shared::cta.global.tile.mbarrier::complete_tx::bytes " \
        "[%0], [%1, {%2, %3, %4}], [%5];" \
        :: "r"(dst), "l"(map), "r"(c0), "r"(c1), "r"(c2), "r"(mbar) : "memory")

#define LDSM4(r, addr) \
    asm volatile("ldmatrix.sync.aligned.m8n8.x4.shared.b16 {%0,%1,%2,%3}, [%4];" \
        : "=r"((r)[0]), "=r"((r)[1]), "=r"((r)[2]), "=r"((r)[3]) : "r"(addr))

#define MMA(acc, a, b0, b1) \
    asm volatile("mma.sync.aligned.m16n8k16.row.col.f32.f16.f16.f32 " \
        "{%0,%1,%2,%3},{%4,%5,%6,%7},{%8,%9},{%0,%1,%2,%3};" \
        : "+f"((acc)[0]), "+f"((acc)[1]), "+f"((acc)[2]), "+f"((acc)[3]) \
        : "r"((a)[0]), "r"((a)[1]), "r"((a)[2]), "r"((a)[3]), "r"(b0), "r"(b1))

// ---------------------------------------------------------------------------
// Fused prologue. z < NIMG : padconvert blocks (x 98 spatial/32, y 4 cblk/64).
//                 z == NIMG: binarize, o = bx*4 + by (first 256 of 392).
// ---------------------------------------------------------------------------
__global__ void prologue_kernel(const float* __restrict__ x, const float* __restrict__ w){
    if (blockIdx.z == NIMG){
        const int o = blockIdx.x * 4 + blockIdx.y;
        if (o >= Oo) return;
        const float* wr = w + (size_t)o * KT;
        __shared__ float red[256];
        float s = 0.f;
        for (int i = threadIdx.x; i < KT; i += 256) s += fabsf(wr[i]);
        red[threadIdx.x] = s;
        __syncthreads();
        #pragma unroll
        for (int off = 128; off > 0; off >>= 1){
            if (threadIdx.x < off) red[threadIdx.x] += red[threadIdx.x + off];
            __syncthreads();
        }
        if (threadIdx.x == 0) g_alpha[o] = red[0] * (1.0f / (float)KT);
        const __half P1 = __float2half(1.0f);
        const __half M1 = __float2half(-1.0f);
        for (int i = threadIdx.x; i < KT; i += 256){
            int c = i / 9, r = i - c * 9;                 // w layout [O][C][3][3]
            g_bsign[(size_t)o * KT + r * Cc + c] = (wr[i] > 0.f) ? P1 : M1;
        }
        return;
    }
    // ---- NCHW f32 -> padded NHWC fp16, half2 stores; pads stay .bss-zero ----
    __shared__ float tile[64][33];
    const int s0 = blockIdx.x * 32, c0 = blockIdx.y * 64, img = blockIdx.z;
    const int t = threadIdx.x;
    #pragma unroll
    for (int j = 0; j < 8; j++){
        int ci = j * 8 + (t >> 5), si = t & 31;
        tile[ci][si] = x[((size_t)(img * Cc + c0 + ci)) * MIMG + s0 + si];
    }
    __syncthreads();
    const int cp = t & 31;                 // channel pair -> 2 contiguous halves
    #pragma unroll
    for (int j = 0; j < 4; j++){
        int si = j * 8 + (t >> 5);
        int s = s0 + si, h = s / Ww, wq = s - h * Ww;
        __half2 v = __halves2half2(__float2half(tile[2*cp][si]),
                                   __float2half(tile[2*cp + 1][si]));
        size_t dst = ((size_t)(img * HP + h + 1) * WP + (wq + 1)) * Cc + c0 + 2*cp;
        *reinterpret_cast<__half2*>(g_xh + dst) = v;
    }
}

// ---------------------------------------------------------------------------
// Producer: one chunk = (kh, kw, cblk). A: signs [128oc][64k] (16KB, oc-half
// selected by o2). B: two x rows (output rows 2t', 2t'+1), each [64 w'][64c]
// via 3D box (c=64, w=64, h=1), OOB-zero for w>=WP.
// ---------------------------------------------------------------------------
__device__ __forceinline__ void issue_chunk(int n, int s, uint32_t data, uint32_t sb,
        int img, int t2, int o2, const CUtensorMap* mW, const CUtensorMap* mX)
{
    const uint32_t st = data + (uint32_t)s * STAGE;
    const uint32_t fb = sb + s * 8;
    const int r = n >> 2, cb = n & 3;
    const int kh = r / 3, kw = r - kh * 3;
    MBAR_EXPECT(fb, STAGE);
    TMA2D(st + OFF_A, mW, n * 64, o2 * 128, fb);
    const int hc = img * HP + 2 * t2 + kh;     // input padded row for out row 2t'
    TMA3D(st + OFF_B0, mX, cb * 64, kw, hc, fb);
    TMA3D(st + OFF_B1, mX, cb * 64, kw, hc + 1, fb);
}

// ---------------------------------------------------------------------------
// Conv GEMM via mma.sync fp16. CTA tile: M=128 (oc half) x 2 output rows x
// N=56. 4 warps; warp w owns 32oc x 56p x 2rows. Each A fragment feeds 14
// MMAs -> smem reads 80KB/chunk/CTA = 89 B/cyc/SM at 2 CTAs/SM (< 128
// crossbar). 2-stage TMA pipeline; sibling CTA hides bubbles.
// ---------------------------------------------------------------------------
__global__ __launch_bounds__(NTHR, 2)
void conv_mma(const __grid_constant__ CUtensorMap mW,
              const __grid_constant__ CUtensorMap mX,
              float* __restrict__ out)
{
    extern __shared__ char smem[];
    const uint32_t sb   = (smem_u32(smem) + 1023u) & ~1023u;
    const uint32_t data = sb + 1024;
    const int tid = threadIdx.x, wid = tid >> 5, l = tid & 31;
    const int t2 = blockIdx.x, o2 = blockIdx.y, img = blockIdx.z;

    // full[s] = sb + s*8 ; empty[s] = sb + 64 + s*8
    if (tid == 0){
        #pragma unroll
        for (int s = 0; s < NSTG; s++){ MBAR_INIT(sb + s*8, 1); MBAR_INIT(sb + 64 + s*8, NTHR); }
    }
    __syncthreads();

    // ---- ldmatrix offsets: UNSWIZZLED base + XOR mask (add ks*32 pre-XOR) ----
    const int mat = l >> 3, lr = l & 7;
    uint32_t abase[2], amask[2], bbase[4], bmask[4];
    #pragma unroll
    for (int mf = 0; mf < 2; mf++){
        uint32_t row = wid * 32 + mf * 16 + (mat & 1) * 8 + lr;   // oc row (0..127)
        abase[mf] = row * 128 + (mat >> 1) * 16;
        amask[mf] = (row & 7) * 16;
    }
    #pragma unroll
    for (int q = 0; q < 4; q++){
        uint32_t row = (2 * q + (mat >> 1)) * 8 + lr;             // p row (w')
        bbase[q] = row * 128 + (mat & 1) * 16;
        bmask[q] = (row & 7) * 16;
    }

    float acc[2][2][7][4];     // [row][mf][nf][4]
    #pragma unroll
    for (int r0 = 0; r0 < 2; r0++)
        #pragma unroll
        for (int i = 0; i < 2; i++)
            #pragma unroll
            for (int j = 0; j < 7; j++)
                #pragma unroll
                for (int k = 0; k < 4; k++) acc[r0][i][j][k] = 0.f;

    // ---- prologue: fill both stages ----
    if (tid == 0){
        #pragma unroll
        for (int n = 0; n < NSTG; n++) issue_chunk(n, n, data, sb, img, t2, o2, &mW, &mX);
    }

    int cs = 0, cph = 0;             // consumer stage/phase
    int pn = NSTG, ps = 0, pph = 0;  // producer next-chunk/stage/phase

    for (int c = 0; c < NCH; c++){
        MBAR_WAIT(sb + cs * 8, cph);
        const uint32_t stA  = data + (uint32_t)cs * STAGE;
        const uint32_t stB0 = stA + OFF_B0;
        const uint32_t stB1 = stA + OFF_B1;

        #pragma unroll
        for (int ks = 0; ks < 4; ks++){
            uint32_t ra[2][4], rb[2][4][4];
            #pragma unroll
            for (int mf = 0; mf < 2; mf++)
                LDSM4(ra[mf], stA + ((abase[mf] + ks * 32) ^ amask[mf]));
            #pragma unroll
            for (int q = 0; q < 4; q++)
                LDSM4(rb[0][q], stB0 + ((bbase[q] + ks * 32) ^ bmask[q]));
            #pragma unroll
            for (int q = 0; q < 4; q++)
                LDSM4(rb[1][q], stB1 + ((bbase[q] + ks * 32) ^ bmask[q]));
            #pragma unroll
            for (int r0 = 0; r0 < 2; r0++)
                #pragma unroll
                for (int mf = 0; mf < 2; mf++)
                    #pragma unroll
                    for (int nf = 0; nf < 7; nf++)
                        MMA(acc[r0][mf][nf], ra[mf],
                            rb[r0][nf >> 1][(nf & 1) * 2], rb[r0][nf >> 1][(nf & 1) * 2 + 1]);
        }

        MBAR_ARRIVE(sb + 64 + cs * 8);
        cs++; if (cs == NSTG){ cs = 0; cph ^= 1; }

        if (tid == 0 && pn < NCH){
            MBAR_WAIT(sb + 64 + ps * 8, pph);      // stage drained by all consumers
            issue_chunk(pn, ps, data, sb, img, t2, o2, &mW, &mX);
            pn++; ps++; if (ps == NSTG){ ps = 0; pph ^= 1; }
        }
    }

    // ---- epilogue: fp32 alpha scale; all outputs valid, unconditional ----
    float* outp = out + (size_t)img * Oo * MIMG;
    #pragma unroll
    for (int r0 = 0; r0 < 2; r0++){
        const int mrow = (2 * t2 + r0) * Ww;
        #pragma unroll
        for (int mf = 0; mf < 2; mf++){
            const int oc0 = o2 * 128 + wid * 32 + mf * 16 + (l >> 2);
            const float a0 = __ldg(&g_alpha[oc0]);
            const float a1 = __ldg(&g_alpha[oc0 + 8]);
            #pragma unroll
            for (int nf = 0; nf < 7; nf++){
                const int m = mrow + nf * 8 + 2 * (l & 3);
                float2 v0 = make_float2(acc[r0][mf][nf][0] * a0, acc[r0][mf][nf][1] * a0);
                float2 v1 = make_float2(acc[r0][mf][nf][2] * a1, acc[r0][mf][nf][3] * a1);
                *reinterpret_cast<float2*>(outp + (size_t)oc0 * MIMG + m)       = v0;
                *reinterpret_cast<float2*>(outp + (size_t)(oc0 + 8) * MIMG + m) = v1;
            }
        }
    }
}

// ---------------------------------------------------------------------------
typedef CUresult (*PFN_tmEnc)(CUtensorMap*, CUtensorMapDataType, cuuint32_t, void*,
                              const cuuint64_t*, const cuuint64_t*, const cuuint32_t*,
                              const cuuint32_t*, CUtensorMapInterleave, CUtensorMapSwizzle,
                              CUtensorMapL2promotion, CUtensorMapFloatOOBfill);

extern "C" void kernel_launch(void* const* d_in, const int* in_sizes, int n_in,
                              void* d_out, int out_size){
    const float* x = (const float*)d_in[0];
    const float* w = (const float*)d_in[1];
    if (n_in >= 2 && in_sizes[0] == Oo * KT && in_sizes[1] != Oo * KT){
        x = (const float*)d_in[1];
        w = (const float*)d_in[0];
    }

    void *pxh = nullptr, *pw = nullptr;
    cudaGetSymbolAddress(&pxh, g_xh);
    cudaGetSymbolAddress(&pw,  g_bsign);

    PFN_tmEnc enc = nullptr;
    cudaDriverEntryPointQueryResult qr;
    cudaGetDriverEntryPointByVersion("cuTensorMapEncodeTiled", (void**)&enc, 12000,
                                     cudaEnableDefault, &qr);

    CUtensorMap mW, mX;
    {   // signs: 2D [k=2304][oc=256], box (64, 128), SW128
        cuuint64_t dim[2]   = {KT, Oo};
        cuuint64_t strd[1]  = {KT * 2};
        cuuint32_t box[2]   = {64, 128};
        cuuint32_t est[2]   = {1, 1};
        enc(&mW, CU_TENSOR_MAP_DATA_TYPE_FLOAT16, 2, pw, dim, strd, box, est,
            CU_TENSOR_MAP_INTERLEAVE_NONE, CU_TENSOR_MAP_SWIZZLE_128B,
            CU_TENSOR_MAP_L2_PROMOTION_L2_128B, CU_TENSOR_MAP_FLOAT_OOB_FILL_NONE);
    }
    {   // x plane: 3D [c=256][w=64][img*h=1856], box (64, 64, 1), SW128
        cuuint64_t dim[3]   = {Cc, WP, (cuuint64_t)NIMG * HP};
        cuuint64_t strd[2]  = {Cc * 2, (cuuint64_t)WP * Cc * 2};
        cuuint32_t box[3]   = {64, 64, 1};
        cuuint32_t est[3]   = {1, 1, 1};
        enc(&mX, CU_TENSOR_MAP_DATA_TYPE_FLOAT16, 3, pxh, dim, strd, box, est,
            CU_TENSOR_MAP_INTERLEAVE_NONE, CU_TENSOR_MAP_SWIZZLE_128B,
            CU_TENSOR_MAP_L2_PROMOTION_L2_128B, CU_TENSOR_MAP_FLOAT_OOB_FILL_NONE);
    }

    cudaFuncSetAttribute(conv_mma, cudaFuncAttributeMaxDynamicSharedMemorySize, SMEM_TOTAL);

    prologue_kernel<<<dim3(98, 4, NIMG + 1), 256>>>(x, w);
    conv_mma<<<dim3(28, 2, NIMG), NTHR, SMEM_TOTAL>>>(mW, mX, (float*)d_out);
}